// round 8
// baseline (speedup 1.0000x reference)
#include <cuda_runtime.h>
#include <cuda_fp16.h>
#include <cstdint>

// ---------------------------------------------------------------------------
// PatchNCELoss B=8192 D=128 T=0.07 via mma.sync m16n8k16 fp16 FP16-ACCUM.
// loss[b] = 1/T + log(sum_k exp((S[b,k]-1)/T)) - pos[b]/T
// Dots accumulated in fp16 as two independent K=64 chains, combined in fp32
// in the epilogue (bounds rounding error); scale/bias folded into epilogue
// FFMA. Structure = R4 loop: occ-2, 2-buffer cp.async, fragment-permuted
// gmem layouts for conflict-free LDS.
// ---------------------------------------------------------------------------

#define BN  8192
#define BN2 8320              // 65 * 128
#define DD  128
#define KS  4                 // key splits
#define NC  16                // 128-key chunks per CTA (8192/128/KS)
#define GRID_X 65

#define INV_T    14.285714285714286f
#define SCALE_L2 20.609929155556620f   /* log2(e)/T */

static __device__ __half g_Ap[BN2 * DD];   // fragment-permuted A (normalized)
static __device__ __half g_Bv[BN * DD];    // fragment-permuted v_n keys
static __device__ __half g_Bi[BN * DD];    // fragment-permuted i_n keys
static __device__ float  g_posT[BN2];
static __device__ int    g_orig[BN2];
static __device__ int    g_cnt[2];
static __device__ float  g_partial[KS * BN2];

// smem: A 32KB | B0 32KB | B1 32KB
#define SMEM_TOT 98304

// ---------------------------------------------------------------------------
__device__ __forceinline__ float ex2f(float x) {
    float r; asm("ex2.approx.f32 %0,%1;" : "=f"(r) : "f"(x)); return r;
}
__device__ __forceinline__ float2 h2f2(uint32_t u) {
    __half2 h = *reinterpret_cast<__half2*>(&u);
    return __half22float2(h);
}
__device__ __forceinline__ uint32_t s2u(const void* p) {
    uint32_t a;
    asm("{ .reg .u64 t; cvta.to.shared.u64 t, %1; cvt.u32.u64 %0, t; }"
        : "=r"(a) : "l"(p));
    return a;
}
#define CPA16(dst, src) \
    asm volatile("cp.async.cg.shared.global [%0], [%1], 16;" :: "r"(dst), "l"(src))
#define CP_COMMIT() asm volatile("cp.async.commit_group;" ::: "memory")
#define CP_WAIT1()  asm volatile("cp.async.wait_group 1;" ::: "memory")
#define CP_WAIT0()  asm volatile("cp.async.wait_group 0;" ::: "memory")

#define LDS128(r, a) \
    asm volatile("ld.shared.v4.b32 {%0,%1,%2,%3}, [%4];" \
        : "=r"((r)[0]), "=r"((r)[1]), "=r"((r)[2]), "=r"((r)[3]) : "r"(a))
#define LDS64(r, a) \
    asm volatile("ld.shared.v2.b32 {%0,%1}, [%2];" \
        : "=r"((r)[0]), "=r"((r)[1]) : "r"(a))

// fp16-accumulate MMA: C/D are 2 x .f16x2 regs
__device__ __forceinline__ void mma16816_h(uint32_t* c, const uint32_t* a,
                                           const uint32_t* b) {
    asm volatile(
        "mma.sync.aligned.m16n8k16.row.col.f16.f16.f16.f16 "
        "{%0,%1}, {%2,%3,%4,%5}, {%6,%7}, {%0,%1};"
        : "+r"(c[0]), "+r"(c[1])
        : "r"(a[0]), "r"(a[1]), "r"(a[2]), "r"(a[3]), "r"(b[0]), "r"(b[1]));
}

// fragment-permuted half index helpers
__device__ __forceinline__ int a_perm_idx(int s, int t) {
    int mb = s >> 4, q = s & 15, g = q & 7, hi = q >> 3;
    int kk = t >> 4, tc = t & 15, kh = tc >> 3, t4 = (tc >> 1) & 3, h = tc & 1;
    int lane = g * 4 + t4, r = hi + 2 * kh;
    return (((mb * 8 + kk) * 32 + lane) << 3) + r * 2 + h;
}
__device__ __forceinline__ int b_perm_idx(int b, int t) {
    int nb = b >> 3, g = b & 7;
    int kk = t >> 4, tc = t & 15, kh = tc >> 3, t4 = (tc >> 1) & 3, h = tc & 1;
    int lane = g * 4 + t4;
    return (((nb * 8 + kk) * 32 + lane) << 2) + kh * 2 + h;
}

// ---------------------------------------------------------------------------
__global__ void init_kernel() {
    if (threadIdx.x == 0) { g_cnt[0] = 0; g_cnt[1] = 0; }
}

__global__ void prep_kernel(const float* __restrict__ fv,
                            const float* __restrict__ fi,
                            const float* __restrict__ v,
                            const float* __restrict__ vi) {
    int b = blockIdx.x;
    int t = threadIdx.x;
    float xfv = fv[b * DD + t];
    float xfi = fi[b * DD + t];
    float xv  = v [b * DD + t];
    float xi  = vi[b * DD + t];

    float s[6];
    s[0] = xfv * xfv; s[1] = xfi * xfi; s[2] = xv * xv;
    s[3] = xi * xi;   s[4] = xfv * xv;  s[5] = xfi * xi;
#pragma unroll
    for (int off = 16; off; off >>= 1)
#pragma unroll
        for (int k = 0; k < 6; ++k)
            s[k] += __shfl_xor_sync(0xffffffffu, s[k], off);

    __shared__ float sh[4][6];
    __shared__ float bc[3];
    __shared__ int   bsl[2];
    int w = t >> 5, lane = t & 31;
    if (lane == 0)
#pragma unroll
        for (int k = 0; k < 6; ++k) sh[w][k] = s[k];
    __syncthreads();

    if (t == 0) {
        float tot[6];
#pragma unroll
        for (int k = 0; k < 6; ++k)
            tot[k] = sh[0][k] + sh[1][k] + sh[2][k] + sh[3][k];
        float inv_fv = 1.f / fmaxf(sqrtf(tot[0]), 1e-12f);
        float inv_fi = 1.f / fmaxf(sqrtf(tot[1]), 1e-12f);
        float inv_v  = 1.f / fmaxf(sqrtf(tot[2]), 1e-12f);
        float inv_i  = 1.f / fmaxf(sqrtf(tot[3]), 1e-12f);
        float pos_v = tot[4] * inv_fv * inv_v;
        float pos_i = tot[5] * inv_fi * inv_i;
        bool use_v = (pos_v >= pos_i);
        int slot = use_v ? atomicAdd(&g_cnt[0], 1)
                         : (BN2 - 1 - atomicAdd(&g_cnt[1], 1));
        g_orig[slot] = b;
        g_posT[slot] = (use_v ? pos_v : pos_i) * INV_T;
        bc[0] = inv_v; bc[1] = inv_i; bc[2] = use_v ? inv_fv : inv_fi;
        bsl[0] = slot; bsl[1] = use_v ? 1 : 0;
    }
    __syncthreads();

    g_Bv[b_perm_idx(b, t)] = __float2half_rn(xv * bc[0]);
    g_Bi[b_perm_idx(b, t)] = __float2half_rn(xi * bc[1]);
    g_Ap[a_perm_idx(bsl[0], t)] =
        __float2half_rn((bsl[1] ? xfv : xfi) * bc[2]);
}

__global__ void zero_pad_kernel() {
    int row = g_cnt[0] + blockIdx.x;
    int t = threadIdx.x;
    g_Ap[a_perm_idx(row, t)] = __float2half_rn(0.f);
    if (t == 0) g_orig[row] = -1;
}

// ---------------------------------------------------------------------------
__global__ __launch_bounds__(256, 2) void gemm_lse_kernel() {
    extern __shared__ __align__(16) unsigned char sm[];
    __shared__ float red[128][4];

    const uint32_t smA  = s2u(sm);
    const uint32_t smB0 = smA + 32768u;
    const uint32_t smB1 = smA + 65536u;

    const int tid  = threadIdx.x;
    const int lane = tid & 31;
    const int wid  = tid >> 5;
    const int wm = wid >> 2;          // 0..1  (64-row block)
    const int wn = wid & 3;           // 0..3  (32-key block)

    const int c0 = g_cnt[0];
    const int bx = blockIdx.x, ks = blockIdx.y;
    const int grp = (bx > (c0 >> 7)) ? 1 : 0;
    const int row0 = bx << 7;
    const char* __restrict__ Kb = (const char*)(grp ? g_Bi : g_Bv);

    // A tile + B chunk 0
    {
        const char* Asrc = (const char*)g_Ap + (size_t)row0 * 256;
#pragma unroll
        for (int q = 0; q < 8; ++q) {
            int i = (tid + q * 256) * 16;
            CPA16(smA + (uint32_t)i, Asrc + i);
        }
        const char* Bsrc = Kb + (size_t)ks * 32768;
#pragma unroll
        for (int q = 0; q < 8; ++q) {
            int i = (tid + q * 256) * 16;
            CPA16(smB0 + (uint32_t)i, Bsrc + i);
        }
        CP_COMMIT();
    }

    float rsum[8];
#pragma unroll
    for (int i = 0; i < 8; ++i) rsum[i] = 0.f;

    const uint32_t aoff = smA + (uint32_t)(wm * 16384 + lane * 16);
    const uint32_t boff = (uint32_t)(wn * 8192 + lane * 8);

#pragma unroll 1
    for (int ci = 0; ci < NC; ++ci) {
        if (ci + 1 < NC) {
            const char* Bsrc = Kb + (size_t)(ks + (ci + 1) * KS) * 32768;
            uint32_t dst = ((ci + 1) & 1) ? smB1 : smB0;
#pragma unroll
            for (int q = 0; q < 8; ++q) {
                int i = (tid + q * 256) * 16;
                CPA16(dst + (uint32_t)i, Bsrc + i);
            }
            CP_COMMIT();
            CP_WAIT1();
        } else {
            CP_WAIT0();
        }
        __syncthreads();

        const uint32_t sB = ((ci & 1) ? smB1 : smB0) + boff;
        const uint32_t sA = smA + (uint32_t)(wm * 16384 + lane * 16);
        (void)aoff;

        // fp16 accumulators: [mi][ni][chain][reg], chain = K half
        uint32_t c[4][4][2][2];
#pragma unroll
        for (int mi = 0; mi < 4; ++mi)
#pragma unroll
            for (int ni = 0; ni < 4; ++ni)
#pragma unroll
                for (int h = 0; h < 2; ++h)
                    c[mi][ni][h][0] = c[mi][ni][h][1] = 0u;

#pragma unroll
        for (int kk = 0; kk < 8; ++kk) {
            const int ch = kk >> 2;
            uint32_t a[4][4], b[4][2];
#pragma unroll
            for (int mi = 0; mi < 4; ++mi)
                LDS128(a[mi], sA + (uint32_t)(mi * 4096 + kk * 512));
#pragma unroll
            for (int ni = 0; ni < 4; ++ni)
                LDS64(b[ni], sB + (uint32_t)(ni * 2048 + kk * 256));
#pragma unroll
            for (int mi = 0; mi < 4; ++mi)
#pragma unroll
                for (int ni = 0; ni < 4; ++ni)
                    mma16816_h(c[mi][ni][ch], a[mi], b[ni]);
        }

        // epilogue: combine chains in fp32, exp((s-1)/T), fixed order
#pragma unroll
        for (int mi = 0; mi < 4; ++mi) {
            float s0 = 0.f, s1 = 0.f;
#pragma unroll
            for (int ni = 0; ni < 4; ++ni) {
                float2 p0 = h2f2(c[mi][ni][0][0]);   // row r, 2 cols
                float2 q0 = h2f2(c[mi][ni][1][0]);
                float2 p1 = h2f2(c[mi][ni][0][1]);   // row r+8, 2 cols
                float2 q1 = h2f2(c[mi][ni][1][1]);
                float e0 = p0.x + q0.x, e1 = p0.y + q0.y;
                float e2 = p1.x + q1.x, e3 = p1.y + q1.y;
                s0 += ex2f(fmaf(e0, SCALE_L2, -SCALE_L2)) +
                      ex2f(fmaf(e1, SCALE_L2, -SCALE_L2));
                s1 += ex2f(fmaf(e2, SCALE_L2, -SCALE_L2)) +
                      ex2f(fmaf(e3, SCALE_L2, -SCALE_L2));
            }
            rsum[mi * 2]     += s0;
            rsum[mi * 2 + 1] += s1;
        }
        __syncthreads();
    }

    // reduce across the 4 col-lanes of each row
#pragma unroll
    for (int mi = 0; mi < 4; ++mi)
#pragma unroll
        for (int h = 0; h < 2; ++h) {
            float val = rsum[mi * 2 + h];
            val += __shfl_xor_sync(0xffffffffu, val, 1);
            val += __shfl_xor_sync(0xffffffffu, val, 2);
            if ((lane & 3) == 0)
                red[wm * 64 + mi * 16 + h * 8 + (lane >> 2)][wn] = val;
        }
    __syncthreads();

    if (tid < 128) {
        int slot = row0 + tid;
        float sum = red[tid][0] + red[tid][1] + red[tid][2] + red[tid][3];
        g_partial[ks * BN2 + slot] = sum;
    }
}

// ---------------------------------------------------------------------------
__global__ void finalize_kernel(float* __restrict__ out) {
    int s = blockIdx.x * 256 + threadIdx.x;
    if (s < BN2) {
        int o = g_orig[s];
        if (o >= 0) {
            float sum = g_partial[s] + g_partial[BN2 + s] +
                        g_partial[2 * BN2 + s] + g_partial[3 * BN2 + s];
            out[o] = INV_T + logf(sum) - g_posT[s];
        }
    }
}

// ---------------------------------------------------------------------------
extern "C" void kernel_launch(void* const* d_in, const int* in_sizes, int n_in,
                              void* d_out, int out_size) {
    (void)in_sizes; (void)n_in; (void)out_size;
    const float* fv = (const float*)d_in[0];
    const float* fi = (const float*)d_in[1];
    const float* v  = (const float*)d_in[2];
    const float* vi = (const float*)d_in[3];
    float* out = (float*)d_out;

    cudaFuncSetAttribute(gemm_lse_kernel,
                         cudaFuncAttributeMaxDynamicSharedMemorySize, SMEM_TOT);

    init_kernel<<<1, 32>>>();
    prep_kernel<<<BN, 128>>>(fv, fi, v, vi);
    zero_pad_kernel<<<128, 128>>>();
    gemm_lse_kernel<<<dim3(GRID_X, KS), 256, SMEM_TOT>>>();
    finalize_kernel<<<(BN2 + 255) / 256, 256>>>(out);
}

// round 9
// speedup vs baseline: 1.0732x; 1.0732x over previous
#include <cuda_runtime.h>
#include <cuda_fp16.h>
#include <cstdint>

// ---------------------------------------------------------------------------
// PatchNCELoss B=8192 D=128 T=0.07 via mma.sync m16n8k16 fp16 (HMMA, f32 acc).
// loss[b] = 1/T + log(sum_k exp((S[b,k]-1)/T)) - pos[b]/T
// 3 kernels: prep (warp/row, compaction, fp16 fragment-permuted scatter),
// gemm+exp-sum (R4 schedule, A pre-scaled by log2(e)/T, acc init -log2(e)/T),
// finalize (log + pos/T). g_cnt reset by last gemm block; pad rows never
// zeroed (row-independent, discarded by range test in finalize).
// ---------------------------------------------------------------------------

#define BN  8192
#define BN2 8320              // 65 * 128
#define DD  128
#define KS  4                 // key splits
#define NC  16                // 128-key chunks per CTA (8192/128/KS)
#define GRID_X 65

#define INV_T    14.285714285714286f
#define SCALE_L2 20.609929155556620f   /* log2(e)/T */

static __device__ __half g_Ap[BN2 * DD];   // fragment-permuted A * SCALE_L2
static __device__ __half g_Bv[BN * DD];    // fragment-permuted v_n keys
static __device__ __half g_Bi[BN * DD];    // fragment-permuted i_n keys
static __device__ float  g_posT[BN2];
static __device__ int    g_orig[BN2];
static __device__ int    g_cnt[2];
static __device__ int    g_done;
static __device__ int    g_c0s;
static __device__ float  g_partial[KS * BN2];

// smem: A 32KB | B0 32KB | B1 32KB
#define SMEM_TOT 98304

// ---------------------------------------------------------------------------
__device__ __forceinline__ float ex2f(float x) {
    float r; asm("ex2.approx.f32 %0,%1;" : "=f"(r) : "f"(x)); return r;
}
__device__ __forceinline__ uint32_t s2u(const void* p) {
    uint32_t a;
    asm("{ .reg .u64 t; cvta.to.shared.u64 t, %1; cvt.u32.u64 %0, t; }"
        : "=r"(a) : "l"(p));
    return a;
}
#define CPA16(dst, src) \
    asm volatile("cp.async.cg.shared.global [%0], [%1], 16;" :: "r"(dst), "l"(src))
#define CP_COMMIT() asm volatile("cp.async.commit_group;" ::: "memory")
#define CP_WAIT1()  asm volatile("cp.async.wait_group 1;" ::: "memory")
#define CP_WAIT0()  asm volatile("cp.async.wait_group 0;" ::: "memory")

#define LDS128(r, a) \
    asm volatile("ld.shared.v4.b32 {%0,%1,%2,%3}, [%4];" \
        : "=r"((r)[0]), "=r"((r)[1]), "=r"((r)[2]), "=r"((r)[3]) : "r"(a))
#define LDS64(r, a) \
    asm volatile("ld.shared.v2.b32 {%0,%1}, [%2];" \
        : "=r"((r)[0]), "=r"((r)[1]) : "r"(a))

__device__ __forceinline__ void mma16816(float* c, const uint32_t* a,
                                         const uint32_t* b) {
    asm volatile(
        "mma.sync.aligned.m16n8k16.row.col.f32.f16.f16.f32 "
        "{%0,%1,%2,%3}, {%4,%5,%6,%7}, {%8,%9}, {%0,%1,%2,%3};"
        : "+f"(c[0]), "+f"(c[1]), "+f"(c[2]), "+f"(c[3])
        : "r"(a[0]), "r"(a[1]), "r"(a[2]), "r"(a[3]), "r"(b[0]), "r"(b[1]));
}

// fragment-permuted half index helpers
__device__ __forceinline__ int a_perm_idx(int s, int t) {
    int mb = s >> 4, q = s & 15, g = q & 7, hi = q >> 3;
    int kk = t >> 4, tc = t & 15, kh = tc >> 3, t4 = (tc >> 1) & 3, h = tc & 1;
    int lane = g * 4 + t4, r = hi + 2 * kh;
    return (((mb * 8 + kk) * 32 + lane) << 3) + r * 2 + h;
}
__device__ __forceinline__ int b_perm_idx(int b, int t) {
    int nb = b >> 3, g = b & 7;
    int kk = t >> 4, tc = t & 15, kh = tc >> 3, t4 = (tc >> 1) & 3, h = tc & 1;
    int lane = g * 4 + t4;
    return (((nb * 8 + kk) * 32 + lane) << 2) + kh * 2 + h;
}

// ---------------------------------------------------------------------------
// warp-per-row prep: norms, diag dots, branch select, compaction, scatter.
__global__ __launch_bounds__(256) void prep_kernel(
        const float* __restrict__ fv, const float* __restrict__ fi,
        const float* __restrict__ v,  const float* __restrict__ vi) {
    int b    = blockIdx.x * 8 + (threadIdx.x >> 5);
    int lane = threadIdx.x & 31;

    float4 xfv = *(const float4*)(fv + b * DD + lane * 4);
    float4 xfi = *(const float4*)(fi + b * DD + lane * 4);
    float4 xv  = *(const float4*)(v  + b * DD + lane * 4);
    float4 xi  = *(const float4*)(vi + b * DD + lane * 4);

    float s[6];
    s[0] = xfv.x*xfv.x + xfv.y*xfv.y + xfv.z*xfv.z + xfv.w*xfv.w;
    s[1] = xfi.x*xfi.x + xfi.y*xfi.y + xfi.z*xfi.z + xfi.w*xfi.w;
    s[2] = xv.x*xv.x   + xv.y*xv.y   + xv.z*xv.z   + xv.w*xv.w;
    s[3] = xi.x*xi.x   + xi.y*xi.y   + xi.z*xi.z   + xi.w*xi.w;
    s[4] = xfv.x*xv.x  + xfv.y*xv.y  + xfv.z*xv.z  + xfv.w*xv.w;
    s[5] = xfi.x*xi.x  + xfi.y*xi.y  + xfi.z*xi.z  + xfi.w*xi.w;
#pragma unroll
    for (int off = 16; off; off >>= 1)
#pragma unroll
        for (int k = 0; k < 6; ++k)
            s[k] += __shfl_xor_sync(0xffffffffu, s[k], off);

    // all lanes hold identical totals (fp add is commutative -> bitwise equal)
    float inv_fv = 1.f / fmaxf(sqrtf(s[0]), 1e-12f);
    float inv_fi = 1.f / fmaxf(sqrtf(s[1]), 1e-12f);
    float inv_v  = 1.f / fmaxf(sqrtf(s[2]), 1e-12f);
    float inv_i  = 1.f / fmaxf(sqrtf(s[3]), 1e-12f);
    float pos_v = s[4] * inv_fv * inv_v;
    float pos_i = s[5] * inv_fi * inv_i;
    bool use_v = (pos_v >= pos_i);

    int slot = 0;
    if (lane == 0) {
        slot = use_v ? atomicAdd(&g_cnt[0], 1)
                     : (BN2 - 1 - atomicAdd(&g_cnt[1], 1));
        g_orig[slot] = b;
        g_posT[slot] = (use_v ? pos_v : pos_i) * INV_T;
    }
    slot = __shfl_sync(0xffffffffu, slot, 0);

    float af = (use_v ? inv_fv : inv_fi) * SCALE_L2;
    float aval[4] = { use_v ? xfv.x : xfi.x, use_v ? xfv.y : xfi.y,
                      use_v ? xfv.z : xfi.z, use_v ? xfv.w : xfi.w };
    float vval[4] = { xv.x, xv.y, xv.z, xv.w };
    float ival[4] = { xi.x, xi.y, xi.z, xi.w };
#pragma unroll
    for (int j = 0; j < 4; ++j) {
        int t = lane * 4 + j;
        g_Bv[b_perm_idx(b, t)] = __float2half_rn(vval[j] * inv_v);
        g_Bi[b_perm_idx(b, t)] = __float2half_rn(ival[j] * inv_i);
        g_Ap[a_perm_idx(slot, t)] = __float2half_rn(aval[j] * af);
    }
}

// ---------------------------------------------------------------------------
__global__ __launch_bounds__(256, 2) void gemm_lse_kernel() {
    extern __shared__ __align__(16) unsigned char sm[];
    __shared__ float red[128][4];

    const uint32_t smA  = s2u(sm);
    const uint32_t smB0 = smA + 32768u;
    const uint32_t smB1 = smA + 65536u;

    const int tid  = threadIdx.x;
    const int lane = tid & 31;
    const int wid  = tid >> 5;
    const int wm = wid >> 2;          // 0..1  (64-row block)
    const int wn = wid & 3;           // 0..3  (32-key block)

    const int c0 = g_cnt[0];
    const int bx = blockIdx.x, ks = blockIdx.y;
    const int grp = (bx > (c0 >> 7)) ? 1 : 0;
    const int row0 = bx << 7;
    const char* __restrict__ Kb = (const char*)(grp ? g_Bi : g_Bv);

    // A tile + B chunk 0
    {
        const char* Asrc = (const char*)g_Ap + (size_t)row0 * 256;
#pragma unroll
        for (int q = 0; q < 8; ++q) {
            int i = (tid + q * 256) * 16;
            CPA16(smA + (uint32_t)i, Asrc + i);
        }
        const char* Bsrc = Kb + (size_t)ks * 32768;
#pragma unroll
        for (int q = 0; q < 8; ++q) {
            int i = (tid + q * 256) * 16;
            CPA16(smB0 + (uint32_t)i, Bsrc + i);
        }
        CP_COMMIT();
    }

    float rsum[8];
#pragma unroll
    for (int i = 0; i < 8; ++i) rsum[i] = 0.f;

    const uint32_t aoff = smA + (uint32_t)(wm * 16384 + lane * 16);
    const uint32_t boff = (uint32_t)(wn * 8192 + lane * 8);

#pragma unroll 1
    for (int ci = 0; ci < NC; ++ci) {
        if (ci + 1 < NC) {
            const char* Bsrc = Kb + (size_t)(ks + (ci + 1) * KS) * 32768;
            uint32_t dst = ((ci + 1) & 1) ? smB1 : smB0;
#pragma unroll
            for (int q = 0; q < 8; ++q) {
                int i = (tid + q * 256) * 16;
                CPA16(dst + (uint32_t)i, Bsrc + i);
            }
            CP_COMMIT();
            CP_WAIT1();
        } else {
            CP_WAIT0();
        }
        __syncthreads();

        const uint32_t sB = ((ci & 1) ? smB1 : smB0) + boff;

        float c[4][4][4];
#pragma unroll
        for (int mi = 0; mi < 4; ++mi)
#pragma unroll
            for (int ni = 0; ni < 4; ++ni)
#pragma unroll
                for (int x = 0; x < 4; ++x) c[mi][ni][x] = -SCALE_L2;

#pragma unroll
        for (int kk = 0; kk < 8; ++kk) {
            uint32_t a[4][4], b[4][2];
#pragma unroll
            for (int mi = 0; mi < 4; ++mi)
                LDS128(a[mi], aoff + (uint32_t)(mi * 4096 + kk * 512));
#pragma unroll
            for (int ni = 0; ni < 4; ++ni)
                LDS64(b[ni], sB + (uint32_t)(ni * 2048 + kk * 256));
#pragma unroll
            for (int mi = 0; mi < 4; ++mi)
#pragma unroll
                for (int ni = 0; ni < 4; ++ni)
                    mma16816(c[mi][ni], a[mi], b[ni]);
        }

        // epilogue: pure ex2 + add (scale/bias folded into A / acc init)
#pragma unroll
        for (int mi = 0; mi < 4; ++mi) {
            float s0 = 0.f, s1 = 0.f;
#pragma unroll
            for (int ni = 0; ni < 4; ++ni) {
                s0 += ex2f(c[mi][ni][0]) + ex2f(c[mi][ni][1]);
                s1 += ex2f(c[mi][ni][2]) + ex2f(c[mi][ni][3]);
            }
            rsum[mi * 2]     += s0;
            rsum[mi * 2 + 1] += s1;
        }
        __syncthreads();
    }

    // reduce across the 4 col-lanes of each row
#pragma unroll
    for (int mi = 0; mi < 4; ++mi)
#pragma unroll
        for (int h = 0; h < 2; ++h) {
            float val = rsum[mi * 2 + h];
            val += __shfl_xor_sync(0xffffffffu, val, 1);
            val += __shfl_xor_sync(0xffffffffu, val, 2);
            if ((lane & 3) == 0)
                red[wm * 64 + mi * 16 + h * 8 + (lane >> 2)][wn] = val;
        }
    __syncthreads();

    if (tid < 128) {
        int slot = row0 + tid;
        float sum = red[tid][0] + red[tid][1] + red[tid][2] + red[tid][3];
        g_partial[ks * BN2 + slot] = sum;
    }

    // snapshot c0 for finalize; last-finishing block resets counters.
    __syncthreads();
    if (tid == 0) {
        if (bx == 0 && ks == 0) g_c0s = c0;
        __threadfence();
        int old = atomicAdd(&g_done, 1);
        if (old == GRID_X * KS - 1) {
            g_cnt[0] = 0; g_cnt[1] = 0; g_done = 0;
        }
    }
}

// ---------------------------------------------------------------------------
__global__ void finalize_kernel(float* __restrict__ out) {
    int s = blockIdx.x * 256 + threadIdx.x;
    if (s < BN2) {
        int c0 = g_c0s;
        if (s < c0 || s >= c0 + 128) {   // skip the 128 pad slots
            float sum = g_partial[s] + g_partial[BN2 + s] +
                        g_partial[2 * BN2 + s] + g_partial[3 * BN2 + s];
            out[g_orig[s]] = INV_T + logf(sum) - g_posT[s];
        }
    }
}

// ---------------------------------------------------------------------------
extern "C" void kernel_launch(void* const* d_in, const int* in_sizes, int n_in,
                              void* d_out, int out_size) {
    (void)in_sizes; (void)n_in; (void)out_size;
    const float* fv = (const float*)d_in[0];
    const float* fi = (const float*)d_in[1];
    const float* v  = (const float*)d_in[2];
    const float* vi = (const float*)d_in[3];
    float* out = (float*)d_out;

    cudaFuncSetAttribute(gemm_lse_kernel,
                         cudaFuncAttributeMaxDynamicSharedMemorySize, SMEM_TOT);

    prep_kernel<<<BN / 8, 256>>>(fv, fi, v, vi);
    gemm_lse_kernel<<<dim3(GRID_X, KS), 256, SMEM_TOT>>>();
    finalize_kernel<<<(BN2 + 255) / 256, 256>>>(out);
}

// round 10
// speedup vs baseline: 1.1100x; 1.0343x over previous
#include <cuda_runtime.h>
#include <cuda_fp16.h>
#include <cstdint>

// ---------------------------------------------------------------------------
// PatchNCELoss B=8192 D=128 T=0.07 via mma.sync m16n8k16 fp16 (HMMA, f32 acc).
// loss[b] = 1/T + log(sum_k exp((S[b,k]-1)/T)) - pos[b]/T
// R10: prep rewritten to avoid 2B scatter write-amplification:
//   - B perm blocks staged in smem, written out as coalesced 16B chunks
//   - A written row-major by slot to g_At; apack_kernel permutes via smem
// gemm_lse_kernel / finalize unchanged from R9 (A pre-scaled by log2(e)/T,
// accumulators init at -log2(e)/T, occ-2, 2-buffer cp.async).
// ---------------------------------------------------------------------------

#define BN  8192
#define BN2 8320              // 65 * 128
#define DD  128
#define KS  4                 // key splits
#define NC  16                // 128-key chunks per CTA (8192/128/KS)
#define GRID_X 65

#define INV_T    14.285714285714286f
#define SCALE_L2 20.609929155556620f   /* log2(e)/T */

static __device__ __half g_Ap[BN2 * DD];   // fragment-permuted A * SCALE_L2
static __device__ __half g_At[BN2 * DD];   // row-major A (by slot), temp
static __device__ __half g_Bv[BN * DD];    // fragment-permuted v_n keys
static __device__ __half g_Bi[BN * DD];    // fragment-permuted i_n keys
static __device__ float  g_posT[BN2];
static __device__ int    g_orig[BN2];
static __device__ int    g_cnt[2];
static __device__ int    g_done;
static __device__ int    g_c0s;
static __device__ float  g_partial[KS * BN2];

// smem: A 32KB | B0 32KB | B1 32KB
#define SMEM_TOT 98304

// ---------------------------------------------------------------------------
__device__ __forceinline__ float ex2f(float x) {
    float r; asm("ex2.approx.f32 %0,%1;" : "=f"(r) : "f"(x)); return r;
}
__device__ __forceinline__ uint32_t s2u(const void* p) {
    uint32_t a;
    asm("{ .reg .u64 t; cvta.to.shared.u64 t, %1; cvt.u32.u64 %0, t; }"
        : "=r"(a) : "l"(p));
    return a;
}
#define CPA16(dst, src) \
    asm volatile("cp.async.cg.shared.global [%0], [%1], 16;" :: "r"(dst), "l"(src))
#define CP_COMMIT() asm volatile("cp.async.commit_group;" ::: "memory")
#define CP_WAIT1()  asm volatile("cp.async.wait_group 1;" ::: "memory")
#define CP_WAIT0()  asm volatile("cp.async.wait_group 0;" ::: "memory")

#define LDS128(r, a) \
    asm volatile("ld.shared.v4.b32 {%0,%1,%2,%3}, [%4];" \
        : "=r"((r)[0]), "=r"((r)[1]), "=r"((r)[2]), "=r"((r)[3]) : "r"(a))
#define LDS64(r, a) \
    asm volatile("ld.shared.v2.b32 {%0,%1}, [%2];" \
        : "=r"((r)[0]), "=r"((r)[1]) : "r"(a))

__device__ __forceinline__ void mma16816(float* c, const uint32_t* a,
                                         const uint32_t* b) {
    asm volatile(
        "mma.sync.aligned.m16n8k16.row.col.f32.f16.f16.f32 "
        "{%0,%1,%2,%3}, {%4,%5,%6,%7}, {%8,%9}, {%0,%1,%2,%3};"
        : "+f"(c[0]), "+f"(c[1]), "+f"(c[2]), "+f"(c[3])
        : "r"(a[0]), "r"(a[1]), "r"(a[2]), "r"(a[3]), "r"(b[0]), "r"(b[1]));
}

// ---------------------------------------------------------------------------
// warp-per-row prep. B perm staged through smem -> coalesced 16B writes.
// A written row-major by slot (coalesced 8B/lane); permuted later by apack.
__global__ __launch_bounds__(256) void prep_kernel(
        const float* __restrict__ fv, const float* __restrict__ fi,
        const float* __restrict__ v,  const float* __restrict__ vi) {
    __shared__ uint32_t bvs[512];   // 8 rows x 128 halfs (one nb perm block)
    __shared__ uint32_t bis[512];

    int tid  = threadIdx.x;
    int w    = tid >> 5;
    int lane = tid & 31;
    int b    = blockIdx.x * 8 + w;

    float4 xfv = *(const float4*)(fv + b * DD + lane * 4);
    float4 xfi = *(const float4*)(fi + b * DD + lane * 4);
    float4 xv  = *(const float4*)(v  + b * DD + lane * 4);
    float4 xi  = *(const float4*)(vi + b * DD + lane * 4);

    float s[6];
    s[0] = xfv.x*xfv.x + xfv.y*xfv.y + xfv.z*xfv.z + xfv.w*xfv.w;
    s[1] = xfi.x*xfi.x + xfi.y*xfi.y + xfi.z*xfi.z + xfi.w*xfi.w;
    s[2] = xv.x*xv.x   + xv.y*xv.y   + xv.z*xv.z   + xv.w*xv.w;
    s[3] = xi.x*xi.x   + xi.y*xi.y   + xi.z*xi.z   + xi.w*xi.w;
    s[4] = xfv.x*xv.x  + xfv.y*xv.y  + xfv.z*xv.z  + xfv.w*xv.w;
    s[5] = xfi.x*xi.x  + xfi.y*xi.y  + xfi.z*xi.z  + xfi.w*xi.w;
#pragma unroll
    for (int off = 16; off; off >>= 1)
#pragma unroll
        for (int k = 0; k < 6; ++k)
            s[k] += __shfl_xor_sync(0xffffffffu, s[k], off);

    // all lanes hold identical totals (xor-butterfly -> bitwise equal)
    float inv_fv = 1.f / fmaxf(sqrtf(s[0]), 1e-12f);
    float inv_fi = 1.f / fmaxf(sqrtf(s[1]), 1e-12f);
    float inv_v  = 1.f / fmaxf(sqrtf(s[2]), 1e-12f);
    float inv_i  = 1.f / fmaxf(sqrtf(s[3]), 1e-12f);
    float pos_v = s[4] * inv_fv * inv_v;
    float pos_i = s[5] * inv_fi * inv_i;
    bool use_v = (pos_v >= pos_i);

    int slot = 0;
    if (lane == 0) {
        slot = use_v ? atomicAdd(&g_cnt[0], 1)
                     : (BN2 - 1 - atomicAdd(&g_cnt[1], 1));
        g_orig[slot] = b;
        g_posT[slot] = (use_v ? pos_v : pos_i) * INV_T;
    }
    slot = __shfl_sync(0xffffffffu, slot, 0);

    float af = (use_v ? inv_fv : inv_fi) * SCALE_L2;
    float aval[4] = { use_v ? xfv.x : xfi.x, use_v ? xfv.y : xfi.y,
                      use_v ? xfv.z : xfi.z, use_v ? xfv.w : xfi.w };
    float vval[4] = { xv.x * inv_v, xv.y * inv_v, xv.z * inv_v, xv.w * inv_v };
    float ival[4] = { xi.x * inv_i, xi.y * inv_i, xi.z * inv_i, xi.w * inv_i };

    // A: row-major by slot, 8 bytes per lane (coalesced)
    {
        __half2 lo = __halves2half2(__float2half_rn(aval[0] * af),
                                    __float2half_rn(aval[1] * af));
        __half2 hi = __halves2half2(__float2half_rn(aval[2] * af),
                                    __float2half_rn(aval[3] * af));
        uint2 u;
        u.x = *reinterpret_cast<uint32_t*>(&lo);
        u.y = *reinterpret_cast<uint32_t*>(&hi);
        *reinterpret_cast<uint2*>(g_At + (size_t)slot * DD + lane * 4) = u;
    }

    // B: stage perm block in smem (half2 = 4B pieces)
    int g = b & 7;
#pragma unroll
    for (int j = 0; j < 2; ++j) {
        int t0 = lane * 4 + j * 2;
        int kk = t0 >> 4, kh = (t0 >> 3) & 1, t4 = (t0 >> 1) & 3;
        int l2 = (kk * 32 + g * 4 + t4) * 2 + kh;   // half2 index
        __half2 hv = __halves2half2(__float2half_rn(vval[j*2]),
                                    __float2half_rn(vval[j*2+1]));
        __half2 hb = __halves2half2(__float2half_rn(ival[j*2]),
                                    __float2half_rn(ival[j*2+1]));
        bvs[l2] = *reinterpret_cast<uint32_t*>(&hv);
        bis[l2] = *reinterpret_cast<uint32_t*>(&hb);
    }
    __syncthreads();

    // coalesced writeout: 2KB per matrix per block
    if (tid < 128) {
        ((uint4*)(g_Bv + (size_t)blockIdx.x * 1024))[tid] = ((uint4*)bvs)[tid];
    } else {
        int i = tid - 128;
        ((uint4*)(g_Bi + (size_t)blockIdx.x * 1024))[i] = ((uint4*)bis)[i];
    }
}

// ---------------------------------------------------------------------------
// permute g_At (row-major by slot) into g_Ap (fragment order).
// block = 128 slot-rows = 8 mb blocks; each mb block staged via smem.
__global__ __launch_bounds__(256) void apack_kernel() {
    __shared__ uint32_t smu[16 * 64];   // 16 rows x 128 halfs = 4KB
    int tid = threadIdx.x;
    int r0  = blockIdx.x * 128;

    int kk = tid >> 5, lane = tid & 31;
    int g = lane >> 2, t4 = lane & 3;

#pragma unroll 1
    for (int mb = 0; mb < 8; ++mb) {
        int rowbase = r0 + mb * 16;
        // load 16 rows coalesced (16B per thread)
        ((uint4*)smu)[tid] = *(const uint4*)(g_At + (size_t)(rowbase + (tid >> 4)) * DD
                                             + (tid & 15) * 8);
        __syncthreads();

        // gather one 16B perm chunk per thread, store coalesced
        uint4 o;
        o.x = smu[g * 64 + kk * 8 + t4];
        o.y = smu[(g + 8) * 64 + kk * 8 + t4];
        o.z = smu[g * 64 + kk * 8 + 4 + t4];
        o.w = smu[(g + 8) * 64 + kk * 8 + 4 + t4];
        ((uint4*)(g_Ap + (size_t)(blockIdx.x * 8 + mb) * 2048))[tid] = o;
        __syncthreads();
    }
}

// ---------------------------------------------------------------------------
__global__ __launch_bounds__(256, 2) void gemm_lse_kernel() {
    extern __shared__ __align__(16) unsigned char sm[];
    __shared__ float red[128][4];

    const uint32_t smA  = s2u(sm);
    const uint32_t smB0 = smA + 32768u;
    const uint32_t smB1 = smA + 65536u;

    const int tid  = threadIdx.x;
    const int lane = tid & 31;
    const int wid  = tid >> 5;
    const int wm = wid >> 2;          // 0..1  (64-row block)
    const int wn = wid & 3;           // 0..3  (32-key block)

    const int c0 = g_cnt[0];
    const int bx = blockIdx.x, ks = blockIdx.y;
    const int grp = (bx > (c0 >> 7)) ? 1 : 0;
    const int row0 = bx << 7;
    const char* __restrict__ Kb = (const char*)(grp ? g_Bi : g_Bv);

    // A tile + B chunk 0
    {
        const char* Asrc = (const char*)g_Ap + (size_t)row0 * 256;
#pragma unroll
        for (int q = 0; q < 8; ++q) {
            int i = (tid + q * 256) * 16;
            CPA16(smA + (uint32_t)i, Asrc + i);
        }
        const char* Bsrc = Kb + (size_t)ks * 32768;
#pragma unroll
        for (int q = 0; q < 8; ++q) {
            int i = (tid + q * 256) * 16;
            CPA16(smB0 + (uint32_t)i, Bsrc + i);
        }
        CP_COMMIT();
    }

    float rsum[8];
#pragma unroll
    for (int i = 0; i < 8; ++i) rsum[i] = 0.f;

    const uint32_t aoff = smA + (uint32_t)(wm * 16384 + lane * 16);
    const uint32_t boff = (uint32_t)(wn * 8192 + lane * 8);

#pragma unroll 1
    for (int ci = 0; ci < NC; ++ci) {
        if (ci + 1 < NC) {
            const char* Bsrc = Kb + (size_t)(ks + (ci + 1) * KS) * 32768;
            uint32_t dst = ((ci + 1) & 1) ? smB1 : smB0;
#pragma unroll
            for (int q = 0; q < 8; ++q) {
                int i = (tid + q * 256) * 16;
                CPA16(dst + (uint32_t)i, Bsrc + i);
            }
            CP_COMMIT();
            CP_WAIT1();
        } else {
            CP_WAIT0();
        }
        __syncthreads();

        const uint32_t sB = ((ci & 1) ? smB1 : smB0) + boff;

        float c[4][4][4];
#pragma unroll
        for (int mi = 0; mi < 4; ++mi)
#pragma unroll
            for (int ni = 0; ni < 4; ++ni)
#pragma unroll
                for (int x = 0; x < 4; ++x) c[mi][ni][x] = -SCALE_L2;

#pragma unroll
        for (int kk = 0; kk < 8; ++kk) {
            uint32_t a[4][4], b[4][2];
#pragma unroll
            for (int mi = 0; mi < 4; ++mi)
                LDS128(a[mi], aoff + (uint32_t)(mi * 4096 + kk * 512));
#pragma unroll
            for (int ni = 0; ni < 4; ++ni)
                LDS64(b[ni], sB + (uint32_t)(ni * 2048 + kk * 256));
#pragma unroll
            for (int mi = 0; mi < 4; ++mi)
#pragma unroll
                for (int ni = 0; ni < 4; ++ni)
                    mma16816(c[mi][ni], a[mi], b[ni]);
        }

        // epilogue: pure ex2 + add (scale/bias folded into A / acc init)
#pragma unroll
        for (int mi = 0; mi < 4; ++mi) {
            float s0 = 0.f, s1 = 0.f;
#pragma unroll
            for (int ni = 0; ni < 4; ++ni) {
                s0 += ex2f(c[mi][ni][0]) + ex2f(c[mi][ni][1]);
                s1 += ex2f(c[mi][ni][2]) + ex2f(c[mi][ni][3]);
            }
            rsum[mi * 2]     += s0;
            rsum[mi * 2 + 1] += s1;
        }
        __syncthreads();
    }

    // reduce across the 4 col-lanes of each row
#pragma unroll
    for (int mi = 0; mi < 4; ++mi)
#pragma unroll
        for (int h = 0; h < 2; ++h) {
            float val = rsum[mi * 2 + h];
            val += __shfl_xor_sync(0xffffffffu, val, 1);
            val += __shfl_xor_sync(0xffffffffu, val, 2);
            if ((lane & 3) == 0)
                red[wm * 64 + mi * 16 + h * 8 + (lane >> 2)][wn] = val;
        }
    __syncthreads();

    if (tid < 128) {
        int slot = row0 + tid;
        float sum = red[tid][0] + red[tid][1] + red[tid][2] + red[tid][3];
        g_partial[ks * BN2 + slot] = sum;
    }

    // snapshot c0 for finalize; last-finishing block resets counters.
    __syncthreads();
    if (tid == 0) {
        if (bx == 0 && ks == 0) g_c0s = c0;
        __threadfence();
        int old = atomicAdd(&g_done, 1);
        if (old == GRID_X * KS - 1) {
            g_cnt[0] = 0; g_cnt[1] = 0; g_done = 0;
        }
    }
}

// ---------------------------------------------------------------------------
__global__ void finalize_kernel(float* __restrict__ out) {
    int s = blockIdx.x * 256 + threadIdx.x;
    if (s < BN2) {
        int c0 = g_c0s;
        if (s < c0 || s >= c0 + 128) {   // skip the 128 pad slots
            float sum = g_partial[s] + g_partial[BN2 + s] +
                        g_partial[2 * BN2 + s] + g_partial[3 * BN2 + s];
            out[g_orig[s]] = INV_T + logf(sum) - g_posT[s];
        }
    }
}

// ---------------------------------------------------------------------------
extern "C" void kernel_launch(void* const* d_in, const int* in_sizes, int n_in,
                              void* d_out, int out_size) {
    (void)in_sizes; (void)n_in; (void)out_size;
    const float* fv = (const float*)d_in[0];
    const float* fi = (const float*)d_in[1];
    const float* v  = (const float*)d_in[2];
    const float* vi = (const float*)d_in[3];
    float* out = (float*)d_out;

    cudaFuncSetAttribute(gemm_lse_kernel,
                         cudaFuncAttributeMaxDynamicSharedMemorySize, SMEM_TOT);

    prep_kernel<<<BN / 8, 256>>>(fv, fi, v, vi);
    apack_kernel<<<GRID_X, 256>>>();
    gemm_lse_kernel<<<dim3(GRID_X, KS), 256, SMEM_TOT>>>();
    finalize_kernel<<<(BN2 + 255) / 256, 256>>>(out);
}